// round 6
// baseline (speedup 1.0000x reference)
#include <cuda_runtime.h>

#define NB    16
#define NN    4096
#define W     1024
#define MAXP  300
#define IOU_T 0.7f
#define SC_T  0.5f
#define SENT  0xFF800000u
#define FULLM 0xffffffffu

typedef unsigned long long ull;

// Inter-kernel scratch (static __device__: no allocation)
__device__ ull      g_runs[NB][NN];      // sorted 1024-chunks
__device__ ull      g_keys[NB][NN];      // fully sorted
__device__ float4   g_box [NB][W];
__device__ float    g_area[NB][W];
__device__ unsigned g_mask[NB][W][32];   // row i, word w -> suppress bits j=w*32+b

// Exact fdiv_rn(inter,denom) >= 0.7 via guard band (2e-6 rel >> accumulated
// <=3*2^-24 rounding); exact division only inside the band.
__device__ __forceinline__ bool iou_ge(float4 a, float aa, float4 b, float ab) {
    float xx1 = fmaxf(a.x, b.x);
    float yy1 = fmaxf(a.y, b.y);
    float xx2 = fminf(a.z, b.z);
    float yy2 = fminf(a.w, b.w);
    float w = fmaxf(__fadd_rn(xx2, -xx1), 0.0f);
    float h = fmaxf(__fadd_rn(yy2, -yy1), 0.0f);
    float inter = __fmul_rn(w, h);
    float denom = __fadd_rn(__fadd_rn(aa, ab), -inter);
    float td = __fmul_rn(IOU_T, denom);
    if (inter > __fmul_rn(td, 1.000002f)) return true;
    if (inter < __fmul_rn(td, 0.999998f)) return false;
    return __fdiv_rn(inter, denom) >= IOU_T;
}

// ---------------- K1a: sort 1024-chunks (16 images x 4 chunks) -------------
__global__ __launch_bounds__(256, 1)
void k_sort1(const float2* __restrict__ cls)
{
    __shared__ ull sh[1024];
    const int b = blockIdx.x, c = blockIdx.y, t = threadIdx.x;
    const float4* C4 = (const float4*)(cls + (size_t)b * NN) + c * 512;

    float4 a0 = C4[2 * t], a1 = C4[2 * t + 1];
    float sc[4] = { a0.y, a0.w, a1.y, a1.w };
    ull v[4];
    #pragma unroll
    for (int e = 0; e < 4; ++e) {
        unsigned u = (sc[e] > SC_T) ? ~(__float_as_uint(sc[e]) | 0x80000000u) : SENT;
        v[e] = ((ull)u << 32) | (unsigned)(c * 1024 + 4 * t + e);
    }

    for (int k = 2; k <= 1024; k <<= 1) {
        for (int j = k >> 1; j > 0; j >>= 1) {
            if (j >= 128) {
                #pragma unroll
                for (int e = 0; e < 4; ++e) sh[4 * t + e] = v[e];
                __syncthreads();
                #pragma unroll
                for (int e = 0; e < 4; ++e) {
                    int idx = 4 * t + e;
                    ull p = sh[idx ^ j];
                    bool up    = ((idx & k) == 0);
                    bool lower = ((idx & j) == 0);
                    ull mn = (v[e] < p) ? v[e] : p;
                    ull mx = (v[e] < p) ? p : v[e];
                    v[e] = (up == lower) ? mn : mx;
                }
                __syncthreads();
            } else if (j >= 4) {
                int m = j >> 2;
                bool lower = ((t & m) == 0);
                #pragma unroll
                for (int e = 0; e < 4; ++e) {
                    int idx = 4 * t + e;
                    ull p = __shfl_xor_sync(FULLM, v[e], m);
                    bool up = ((idx & k) == 0);
                    ull mn = (v[e] < p) ? v[e] : p;
                    ull mx = (v[e] < p) ? p : v[e];
                    v[e] = (up == lower) ? mn : mx;
                }
            } else if (j == 2) {
                #pragma unroll
                for (int e = 0; e < 2; ++e) {
                    bool up = (((4 * t + e) & k) == 0);
                    if ((v[e] > v[e + 2]) == up) { ull tmp = v[e]; v[e] = v[e + 2]; v[e + 2] = tmp; }
                }
            } else {
                #pragma unroll
                for (int e = 0; e < 4; e += 2) {
                    bool up = (((4 * t + e) & k) == 0);
                    if ((v[e] > v[e + 1]) == up) { ull tmp = v[e]; v[e] = v[e + 1]; v[e + 1] = tmp; }
                }
            }
        }
    }

    #pragma unroll
    for (int e = 0; e < 4; ++e) g_runs[b][c * 1024 + 4 * t + e] = v[e];
}

// merge-path: emit 4 outputs starting at rank r of merge(A[0:n], B[0:m]).
__device__ __forceinline__ void merge4(const ull* __restrict__ A, int n,
                                       const ull* __restrict__ B, int m,
                                       int r, ull* o)
{
    int lo = max(0, r - m), hi = min(r, n);
    while (lo < hi) {
        int mid = (lo + hi) >> 1;
        if (A[mid] <= B[r - 1 - mid]) lo = mid + 1; else hi = mid;
    }
    int a = lo, bb = r - lo;
    #pragma unroll
    for (int e = 0; e < 4; ++e) {
        bool ta = (bb >= m) || (a < n && A[a] < B[bb]);
        o[e] = ta ? A[a++] : B[bb++];
    }
}

// ---------------- K1b: fused two-stage merge (16 CTAs, 64KB smem) ----------
__global__ __launch_bounds__(1024, 1)
void k_merge(const float4* __restrict__ props)
{
    extern __shared__ ull sm_m[];        // 8192 ull = 64KB
    ull* s0 = sm_m;
    ull* s1 = sm_m + 4096;
    const int b = blockIdx.x, t = threadIdx.x;
    const float4* P = props + (size_t)b * NN;

    for (int i = t; i < NN; i += 1024) s0[i] = g_runs[b][i];
    __syncthreads();

    // stage 1: (0,1)->s1[0:2048], (2,3)->s1[2048:4096]
    {
        int half = t >> 9;
        int r = (t & 511) * 4;
        const ull* A = s0 + half * 2048;
        ull o[4];
        merge4(A, 1024, A + 1024, 1024, r, o);
        #pragma unroll
        for (int e = 0; e < 4; ++e) s1[half * 2048 + r + e] = o[e];
    }
    __syncthreads();

    // stage 2: 2048+2048 -> final + window gather
    {
        ull o[4];
        merge4(s1, 2048, s1 + 2048, 2048, 4 * t, o);
        #pragma unroll
        for (int e = 0; e < 4; ++e) {
            int r = 4 * t + e;
            g_keys[b][r] = o[e];
            if (r < W) {
                int oi = (int)(o[e] & 0xffffffffu);
                float4 p = P[oi];
                g_box[b][r]  = p;
                g_area[b][r] = __fmul_rn(__fadd_rn(p.z, -p.x), __fadd_rn(p.w, -p.y));
            }
        }
    }
}

// ------- K2: bit-matrix, 8 rows/warp register tile, folded balance ---------
__global__ __launch_bounds__(1024, 1)
void k_mask()
{
    __shared__ float4 sb[W];
    __shared__ float  sa[W];
    const int b    = blockIdx.x;
    const int q    = blockIdx.y;                 // 0..3
    const int tid  = threadIdx.x;
    const int lane = tid & 31;
    const int wid  = tid >> 5;                   // 0..31

    for (int t = tid; t < W; t += 1024) { sb[t] = g_box[b][t]; sa[t] = g_area[b][t]; }
    __syncthreads();

    const int gw = q * 32 + wid;                 // 0..127
    int    rows[8];
    float4 bi[8];
    float  ai[8];
    int    wlo[8];
    #pragma unroll
    for (int r = 0; r < 4; ++r) {
        rows[r]     = gw * 4 + r;                // low rows 0..511
        rows[r + 4] = 1023 - (gw * 4 + r);       // mirror rows 512..1023
    }
    #pragma unroll
    for (int r = 0; r < 8; ++r) {
        bi[r]  = sb[rows[r]];
        ai[r]  = sa[rows[r]];
        wlo[r] = rows[r] >> 5;
    }

    for (int w = 0; w < 32; ++w) {
        const int    j  = w * 32 + lane;
        const float4 bj = sb[j];
        const float  aj = sa[j];
        #pragma unroll
        for (int r = 0; r < 8; ++r) {
            unsigned bits = 0;
            if (w >= wlo[r]) {                   // uniform per warp
                bool sup = (j > rows[r]) && iou_ge(bi[r], ai[r], bj, aj);
                bits = __ballot_sync(FULLM, sup);
            }
            if (lane == r) g_mask[b][rows[r]][w] = bits;
        }
    }
}

// ---------------- K3: short-chain warp scan + rare exact fallback ----------
__global__ __launch_bounds__(1024, 1)
void k_scan(const float4* __restrict__ props, const float2* __restrict__ cls,
            float* __restrict__ outb, float* __restrict__ outs)
{
    extern __shared__ unsigned char sm[];
    unsigned* s_mask = (unsigned*)sm;                      // 131072 B
    ull*      s_sk   = (ull*)   (sm + 131072);             //   8192 B
    float4*   s_kbox = (float4*)(sm + 139264);             //   4800 B
    float*    s_kar  = (float*) (sm + 144064);             //   1200 B
    int*      s_kept = (int*)   (sm + 145264);             //   1200 B (ORIGINAL idx)
    unsigned* s_inv  = (unsigned*)(sm + 146464);           //    128 B
    int*      s_ctl  = (int*)   (sm + 146592);
    // fallback chunk arrays alias finished mask region
    float4*        c_box  = (float4*)sm;                   // 16384 B
    float*         c_area = (float*)(sm + 16384);          //  4096 B
    int*           c_oi   = (int*)  (sm + 20480);          //  4096 B
    unsigned char* c_sup  = (unsigned char*)(sm + 24576);  //  1024 B

    const int b   = blockIdx.x;
    const int tid = threadIdx.x;
    const int lane = tid & 31, wid = tid >> 5;
    const float4* P = props + (size_t)b * NN;
    const float2* C = cls   + (size_t)b * NN;

    {
        const uint4* gm = (const uint4*)g_mask[b];
        uint4* smv = (uint4*)s_mask;
        for (int i = tid; i < 8192; i += 1024) smv[i] = gm[i];
        s_sk[tid] = g_keys[b][tid];
    }
    __syncthreads();
    {
        bool iv = ((unsigned)(s_sk[tid] >> 32) == SENT);
        unsigned bal = __ballot_sync(FULLM, iv);
        if (lane == 0) s_inv[wid] = bal;
    }
    __syncthreads();

    // ---- warp 0: greedy scan; chain = one broadcast LDS + AND + FFS ----
    if (tid < 32) {
        unsigned r = s_inv[lane];
        int nk = 0; bool done = false;
        for (int blk = 0; blk < 32 && !done; ++blk) {
            unsigned alive = ~__shfl_sync(FULLM, r, blk);
            while (alive) {
                int t2 = __ffs(alive) - 1;
                int i  = blk * 32 + t2;
                if (lane == 0) s_kept[nk] = (int)(s_sk[i] & 0xffffffffu);
                nk++;
                if (nk == MAXP) { done = true; break; }
                r |= s_mask[i * 32 + lane];           // off critical chain
                unsigned roww = s_mask[i * 32 + blk]; // broadcast, on chain
                alive &= ~roww;
                alive &= ~(1u << t2);
            }
        }
        if (lane == 0) s_ctl[0] = nk;
    }
    __syncthreads();

    // ---- exact fallback beyond window (rare; uniform branch) ----
    if (s_ctl[0] < MAXP) {
        {
            int nk0 = s_ctl[0];
            for (int t = tid; t < nk0; t += 1024) {
                int oi = s_kept[t];
                float4 p = P[oi];
                s_kbox[t] = p;
                s_kar[t]  = __fmul_rn(__fadd_rn(p.z, -p.x), __fadd_rn(p.w, -p.y));
            }
        }
        __syncthreads();
        for (int c = 1; c < 4; ++c) {
            int nkc = s_ctl[0];
            if (nkc >= MAXP) break;
            {
                int jg = c * 1024 + tid;
                ull key = g_keys[b][jg];
                int oi = (int)(key & 0xffffffffu);
                float4 pb = P[oi];
                float  pa = __fmul_rn(__fadd_rn(pb.z, -pb.x), __fadd_rn(pb.w, -pb.y));
                unsigned char sp = ((unsigned)(key >> 32) == SENT) ? 1 : 0;
                if (!sp) {
                    for (int k2 = 0; k2 < nkc; ++k2)
                        if (iou_ge(s_kbox[k2], s_kar[k2], pb, pa)) { sp = 1; break; }
                }
                c_box[tid] = pb; c_area[tid] = pa; c_oi[tid] = oi; c_sup[tid] = sp;
            }
            __syncthreads();
            if (tid < 32) {
                unsigned supm = 0;
                for (int w = 0; w < 32; ++w)
                    supm |= (unsigned)c_sup[w * 32 + lane] << w;
                int nk = nkc; bool done2 = false;
                for (int blk = 0; blk < 32 && !done2; ++blk) {
                    unsigned alive = __ballot_sync(FULLM, !((supm >> blk) & 1));
                    while (alive) {
                        int t2 = __ffs(alive) - 1;
                        int li = blk * 32 + t2;
                        float4 bb = c_box[li]; float ba = c_area[li];
                        if (lane == 0) {
                            s_kept[nk] = c_oi[li];
                            s_kbox[nk] = bb; s_kar[nk] = ba;
                        }
                        nk++;
                        if (nk == MAXP) { done2 = true; break; }
                        for (int w = blk; w < 32; ++w) {
                            int j = w * 32 + lane;
                            if (j > li && !((supm >> w) & 1)) {
                                if (iou_ge(bb, ba, c_box[j], c_area[j])) supm |= 1u << w;
                            }
                        }
                        alive &= ~(1u << t2);
                        alive &= __ballot_sync(FULLM, !((supm >> blk) & 1));
                    }
                }
                if (lane == 0) s_ctl[0] = nk;
            }
            __syncthreads();
        }
    }
    __syncthreads();

    // ---- emit ----
    {
        int nk = s_ctl[0];
        int pad_oi = (nk > 0) ? s_kept[nk - 1]
                              : (int)(g_keys[b][NN - 1] & 0xffffffffu);
        for (int t = tid; t < MAXP; t += 1024) {
            int oi = (t < nk) ? s_kept[t] : pad_oi;
            reinterpret_cast<float4*>(outb)[b * MAXP + t] = P[oi];
            outs[b * MAXP + t] = C[oi].y;
        }
    }
}

extern "C" void kernel_launch(void* const* d_in, const int* in_sizes, int n_in,
                              void* d_out, int out_size)
{
    const float4* props = (const float4*)d_in[0];
    const float2* cls   = (const float2*)d_in[1];
    float* outb = (float*)d_out;                          // [16,300,4]
    float* outs = (float*)d_out + NB * MAXP * 4;          // [16,300]

    static int smem_set = 0;
    const int K3_SMEM = 146624;
    const int KM_SMEM = 65536;
    if (!smem_set) {
        cudaFuncSetAttribute(k_scan,  cudaFuncAttributeMaxDynamicSharedMemorySize, K3_SMEM);
        cudaFuncSetAttribute(k_merge, cudaFuncAttributeMaxDynamicSharedMemorySize, KM_SMEM);
        smem_set = 1;
    }
    k_sort1<<<dim3(NB, 4), 256>>>(cls);
    k_merge<<<NB, 1024, KM_SMEM>>>(props);
    k_mask <<<dim3(NB, 4), 1024>>>();
    k_scan <<<NB, 1024, K3_SMEM>>>(props, cls, outb, outs);
}

// round 7
// speedup vs baseline: 2.0015x; 2.0015x over previous
#include <cuda_runtime.h>

#define NB    16
#define NN    4096
#define W     1024
#define MAXP  300
#define IOU_T 0.7f
#define SC_T  0.5f
#define SENT  0xFF800000u
#define FULLM 0xffffffffu

typedef unsigned long long ull;

// Inter-kernel scratch (static __device__: no allocation)
__device__ ull      g_runs [NB][NN];      // sorted 1024-chunks
__device__ ull      g_keys [NB][NN];      // fully sorted
__device__ float4   g_box  [NB][W];
__device__ float    g_area [NB][W];
__device__ unsigned g_maskT[NB][W][32];   // row j, word w -> bits i (i<j suppresses j)

// Exact fdiv_rn(inter,denom) >= 0.7 via guard band (2e-6 rel >> accumulated
// <=3*2^-24 rounding); exact division only inside the band.
__device__ __forceinline__ bool iou_ge(float4 a, float aa, float4 b, float ab) {
    float xx1 = fmaxf(a.x, b.x);
    float yy1 = fmaxf(a.y, b.y);
    float xx2 = fminf(a.z, b.z);
    float yy2 = fminf(a.w, b.w);
    float w = fmaxf(__fadd_rn(xx2, -xx1), 0.0f);
    float h = fmaxf(__fadd_rn(yy2, -yy1), 0.0f);
    float inter = __fmul_rn(w, h);
    float denom = __fadd_rn(__fadd_rn(aa, ab), -inter);
    float td = __fmul_rn(IOU_T, denom);
    if (inter > __fmul_rn(td, 1.000002f)) return true;
    if (inter < __fmul_rn(td, 0.999998f)) return false;
    return __fdiv_rn(inter, denom) >= IOU_T;
}

// ---------------- K1a: sort 1024-chunks (16 images x 4 chunks) -------------
__global__ __launch_bounds__(256, 1)
void k_sort1(const float2* __restrict__ cls)
{
    __shared__ ull sh[1024];
    const int b = blockIdx.x, c = blockIdx.y, t = threadIdx.x;
    const float4* C4 = (const float4*)(cls + (size_t)b * NN) + c * 512;

    float4 a0 = C4[2 * t], a1 = C4[2 * t + 1];
    float sc[4] = { a0.y, a0.w, a1.y, a1.w };
    ull v[4];
    #pragma unroll
    for (int e = 0; e < 4; ++e) {
        unsigned u = (sc[e] > SC_T) ? ~(__float_as_uint(sc[e]) | 0x80000000u) : SENT;
        v[e] = ((ull)u << 32) | (unsigned)(c * 1024 + 4 * t + e);
    }

    for (int k = 2; k <= 1024; k <<= 1) {
        for (int j = k >> 1; j > 0; j >>= 1) {
            if (j >= 128) {
                #pragma unroll
                for (int e = 0; e < 4; ++e) sh[4 * t + e] = v[e];
                __syncthreads();
                #pragma unroll
                for (int e = 0; e < 4; ++e) {
                    int idx = 4 * t + e;
                    ull p = sh[idx ^ j];
                    bool up    = ((idx & k) == 0);
                    bool lower = ((idx & j) == 0);
                    ull mn = (v[e] < p) ? v[e] : p;
                    ull mx = (v[e] < p) ? p : v[e];
                    v[e] = (up == lower) ? mn : mx;
                }
                __syncthreads();
            } else if (j >= 4) {
                int m = j >> 2;
                bool lower = ((t & m) == 0);
                #pragma unroll
                for (int e = 0; e < 4; ++e) {
                    int idx = 4 * t + e;
                    ull p = __shfl_xor_sync(FULLM, v[e], m);
                    bool up = ((idx & k) == 0);
                    ull mn = (v[e] < p) ? v[e] : p;
                    ull mx = (v[e] < p) ? p : v[e];
                    v[e] = (up == lower) ? mn : mx;
                }
            } else if (j == 2) {
                #pragma unroll
                for (int e = 0; e < 2; ++e) {
                    bool up = (((4 * t + e) & k) == 0);
                    if ((v[e] > v[e + 2]) == up) { ull tmp = v[e]; v[e] = v[e + 2]; v[e + 2] = tmp; }
                }
            } else {
                #pragma unroll
                for (int e = 0; e < 4; e += 2) {
                    bool up = (((4 * t + e) & k) == 0);
                    if ((v[e] > v[e + 1]) == up) { ull tmp = v[e]; v[e] = v[e + 1]; v[e + 1] = tmp; }
                }
            }
        }
    }

    #pragma unroll
    for (int e = 0; e < 4; ++e) g_runs[b][c * 1024 + 4 * t + e] = v[e];
}

// merge-path: emit 4 outputs starting at rank r of merge(A[0:n], B[0:m]).
__device__ __forceinline__ void merge4(const ull* __restrict__ A, int n,
                                       const ull* __restrict__ B, int m,
                                       int r, ull* o)
{
    int lo = max(0, r - m), hi = min(r, n);
    while (lo < hi) {
        int mid = (lo + hi) >> 1;
        if (A[mid] <= B[r - 1 - mid]) lo = mid + 1; else hi = mid;
    }
    int a = lo, bb = r - lo;
    #pragma unroll
    for (int e = 0; e < 4; ++e) {
        bool ta = (bb >= m) || (a < n && A[a] < B[bb]);
        o[e] = ta ? A[a++] : B[bb++];
    }
}

// ---------------- K1b: fused two-stage merge (16 CTAs, 64KB smem) ----------
__global__ __launch_bounds__(1024, 1)
void k_merge(const float4* __restrict__ props)
{
    extern __shared__ ull sm_m[];
    ull* s0 = sm_m;
    ull* s1 = sm_m + 4096;
    const int b = blockIdx.x, t = threadIdx.x;
    const float4* P = props + (size_t)b * NN;

    for (int i = t; i < NN; i += 1024) s0[i] = g_runs[b][i];
    __syncthreads();
    {
        int half = t >> 9;
        int r = (t & 511) * 4;
        const ull* A = s0 + half * 2048;
        ull o[4];
        merge4(A, 1024, A + 1024, 1024, r, o);
        #pragma unroll
        for (int e = 0; e < 4; ++e) s1[half * 2048 + r + e] = o[e];
    }
    __syncthreads();
    {
        ull o[4];
        merge4(s1, 2048, s1 + 2048, 2048, 4 * t, o);
        #pragma unroll
        for (int e = 0; e < 4; ++e) {
            int r = 4 * t + e;
            g_keys[b][r] = o[e];
            if (r < W) {
                int oi = (int)(o[e] & 0xffffffffu);
                float4 p = P[oi];
                g_box[b][r]  = p;
                g_area[b][r] = __fmul_rn(__fadd_rn(p.z, -p.x), __fadd_rn(p.w, -p.y));
            }
        }
    }
}

// ------ K2: TRANSPOSED bit-matrix; 2 low + 2 high mirror rows per warp -----
__global__ __launch_bounds__(1024, 1)
void k_mask()
{
    __shared__ float4 sb[W];
    __shared__ float  sa[W];
    const int b    = blockIdx.x;
    const int q    = blockIdx.y;                 // 0..7
    const int tid  = threadIdx.x;
    const int lane = tid & 31;
    const int wid  = tid >> 5;                   // 0..31

    for (int t = tid; t < W; t += 1024) { sb[t] = g_box[b][t]; sa[t] = g_area[b][t]; }
    __syncthreads();

    const int gw = q * 32 + wid;                 // 0..255
    int rows[4] = { 2 * gw, 2 * gw + 1, 1022 - 2 * gw, 1023 - 2 * gw };

    #pragma unroll
    for (int r = 0; r < 4; ++r) {
        const int    j  = rows[r];
        const float4 bj = sb[j];
        const float  aj = sa[j];
        const int   whi = j >> 5;
        for (int w = 0; w <= whi; ++w) {         // uniform per warp
            int i = w * 32 + lane;
            bool sup = (i < j) && iou_ge(bj, aj, sb[i], sa[i]);
            unsigned bits = __ballot_sync(FULLM, sup);
            if (lane == 0) g_maskT[b][j][w] = bits;
        }
    }
}

// ------ K3: parallel greedy fixpoint + rank extraction + rare fallback -----
#define MT_STRIDE 33                             // 33-word rows: conflict-free
__global__ __launch_bounds__(1024, 1)
void k_scan(const float4* __restrict__ props, const float2* __restrict__ cls,
            float* __restrict__ outb, float* __restrict__ outs)
{
    extern __shared__ unsigned char sm[];
    unsigned* s_maskT = (unsigned*)sm;                     // 135168 B (1024x33)
    ull*      s_sk    = (ull*)   (sm + 135168);            //   8192 B
    float4*   s_kbox  = (float4*)(sm + 143360);            //   4800 B
    float*    s_kar   = (float*) (sm + 148160);            //   1200 B
    int*      s_kept  = (int*)   (sm + 149360);            //   1200 B (ORIGINAL idx)
    unsigned* s_alive = (unsigned*)(sm + 150560);          //    128 B
    int*      s_pref  = (int*)   (sm + 150688);            //    128 B
    int*      s_ctl   = (int*)   (sm + 150816);            // [0]=nk [1]=chg
    // fallback chunk arrays alias finished maskT region
    float4*        c_box  = (float4*)sm;                   // 16384 B
    float*         c_area = (float*)(sm + 16384);          //  4096 B
    int*           c_oi   = (int*)  (sm + 20480);          //  4096 B
    unsigned char* c_sup  = (unsigned char*)(sm + 24576);  //  1024 B

    const int b    = blockIdx.x;
    const int tid  = threadIdx.x;
    const int lane = tid & 31, wid = tid >> 5;
    const float4* P = props + (size_t)b * NN;
    const float2* C = cls   + (size_t)b * NN;

    // stage maskT (padded rows) + window keys
    {
        const unsigned* gm = (const unsigned*)g_maskT[b];
        for (int idx = tid; idx < W * 32; idx += 1024) {
            int j = idx >> 5, w = idx & 31;
            s_maskT[j * MT_STRIDE + w] = gm[idx];
        }
        s_sk[tid] = g_keys[b][tid];
        if (tid == 0) s_ctl[1] = 0;
    }
    __syncthreads();
    const bool va = ((unsigned)(s_sk[tid] >> 32) != SENT);
    {
        unsigned bal = __ballot_sync(FULLM, va);
        if (lane == 0) s_alive[wid] = bal;
    }
    __syncthreads();

    // ---- Jacobi fixpoint of greedy recurrence (exact at convergence) ----
    const unsigned* mrow = s_maskT + tid * MT_STRIDE;
    for (;;) {
        unsigned sup = 0;
        for (int w = 0; w <= wid; ++w)            // uniform per warp
            sup |= mrow[w] & s_alive[w];
        bool na = va && (sup == 0);
        unsigned nb = __ballot_sync(FULLM, na);
        __syncthreads();                          // old-alive reads done
        if (lane == 0 && nb != s_alive[wid]) { s_alive[wid] = nb; s_ctl[1] = 1; }
        __syncthreads();
        int ch = s_ctl[1];
        __syncthreads();                          // all read ch before clear
        if (!ch) break;
        if (tid == 0) s_ctl[1] = 0;
        __syncthreads();
    }

    // ---- rank extraction ----
    if (tid < 32) {
        unsigned aw = s_alive[lane];
        int c = __popc(aw);
        int inc = c;
        #pragma unroll
        for (int d = 1; d < 32; d <<= 1) {
            int y = __shfl_up_sync(FULLM, inc, d);
            if (lane >= d) inc += y;
        }
        s_pref[lane] = inc - c;
        if (lane == 31) s_ctl[0] = inc;           // nk in window (may exceed MAXP)
    }
    __syncthreads();
    {
        unsigned aw = s_alive[wid];
        if (aw & (1u << lane)) {
            int rank = s_pref[wid] + __popc(aw & ((1u << lane) - 1));
            if (rank < MAXP) s_kept[rank] = (int)(s_sk[tid] & 0xffffffffu);
        }
    }
    __syncthreads();

    // ---- exact fallback beyond window (rare; uniform branch) ----
    if (s_ctl[0] < MAXP) {
        {
            int nk0 = s_ctl[0];
            for (int t = tid; t < nk0; t += 1024) {
                int oi = s_kept[t];
                float4 p = P[oi];
                s_kbox[t] = p;
                s_kar[t]  = __fmul_rn(__fadd_rn(p.z, -p.x), __fadd_rn(p.w, -p.y));
            }
        }
        __syncthreads();
        for (int c = 1; c < 4; ++c) {
            int nkc = s_ctl[0];
            if (nkc >= MAXP) break;
            {
                int jg = c * 1024 + tid;
                ull key = g_keys[b][jg];
                int oi = (int)(key & 0xffffffffu);
                float4 pb = P[oi];
                float  pa = __fmul_rn(__fadd_rn(pb.z, -pb.x), __fadd_rn(pb.w, -pb.y));
                unsigned char sp = ((unsigned)(key >> 32) == SENT) ? 1 : 0;
                if (!sp) {
                    for (int k2 = 0; k2 < nkc; ++k2)
                        if (iou_ge(s_kbox[k2], s_kar[k2], pb, pa)) { sp = 1; break; }
                }
                c_box[tid] = pb; c_area[tid] = pa; c_oi[tid] = oi; c_sup[tid] = sp;
            }
            __syncthreads();
            if (tid < 32) {
                unsigned supm = 0;
                for (int w = 0; w < 32; ++w)
                    supm |= (unsigned)c_sup[w * 32 + lane] << w;
                int nk = nkc; bool done2 = false;
                for (int blk = 0; blk < 32 && !done2; ++blk) {
                    unsigned alive = __ballot_sync(FULLM, !((supm >> blk) & 1));
                    while (alive) {
                        int t2 = __ffs(alive) - 1;
                        int li = blk * 32 + t2;
                        float4 bb = c_box[li]; float ba = c_area[li];
                        if (lane == 0) {
                            s_kept[nk] = c_oi[li];
                            s_kbox[nk] = bb; s_kar[nk] = ba;
                        }
                        nk++;
                        if (nk == MAXP) { done2 = true; break; }
                        for (int w = blk; w < 32; ++w) {
                            int j = w * 32 + lane;
                            if (j > li && !((supm >> w) & 1)) {
                                if (iou_ge(bb, ba, c_box[j], c_area[j])) supm |= 1u << w;
                            }
                        }
                        alive &= ~(1u << t2);
                        alive &= __ballot_sync(FULLM, !((supm >> blk) & 1));
                    }
                }
                if (lane == 0) s_ctl[0] = nk;
            }
            __syncthreads();
        }
    }
    __syncthreads();

    // ---- emit ----
    {
        int nk = s_ctl[0];
        int nkc = (nk < MAXP) ? nk : MAXP;
        int pad_oi = (nk > 0) ? s_kept[nkc - 1]
                              : (int)(g_keys[b][NN - 1] & 0xffffffffu);
        for (int t = tid; t < MAXP; t += 1024) {
            int oi = (t < nk) ? s_kept[t] : pad_oi;
            reinterpret_cast<float4*>(outb)[b * MAXP + t] = P[oi];
            outs[b * MAXP + t] = C[oi].y;
        }
    }
}

extern "C" void kernel_launch(void* const* d_in, const int* in_sizes, int n_in,
                              void* d_out, int out_size)
{
    const float4* props = (const float4*)d_in[0];
    const float2* cls   = (const float2*)d_in[1];
    float* outb = (float*)d_out;                          // [16,300,4]
    float* outs = (float*)d_out + NB * MAXP * 4;          // [16,300]

    static int smem_set = 0;
    const int K3_SMEM = 150848;
    const int KM_SMEM = 65536;
    if (!smem_set) {
        cudaFuncSetAttribute(k_scan,  cudaFuncAttributeMaxDynamicSharedMemorySize, K3_SMEM);
        cudaFuncSetAttribute(k_merge, cudaFuncAttributeMaxDynamicSharedMemorySize, KM_SMEM);
        smem_set = 1;
    }
    k_sort1<<<dim3(NB, 4), 256>>>(cls);
    k_merge<<<NB, 1024, KM_SMEM>>>(props);
    k_mask <<<dim3(NB, 8), 1024>>>();
    k_scan <<<NB, 1024, K3_SMEM>>>(props, cls, outb, outs);
}